// round 17
// baseline (speedup 1.0000x reference)
#include <cuda_runtime.h>
#include <cuda_fp16.h>
#include <cstdint>

#define BB   8
#define TT   2048
#define NXC  1024
#define NHC  1024
#define MTOT (BB * TT)   // 16384

// ---------------------------------------------------------------------------
// Scratch (device globals — no allocation allowed anywhere). Pure fp16.
// ---------------------------------------------------------------------------
__device__ __half g_xh[(size_t)MTOT * NXC];
__device__ __half g_wqkh[2 * NHC * NXC];          // [Wq ; Wk] packed
__device__ __half g_wvh[NHC * NXC], g_woh[NHC * NHC];
__device__ __half g_qkh[(size_t)MTOT * 2 * NHC];  // q|k interleaved, row stride 2048
__device__ __half g_vth[(size_t)NHC * MTOT];
__device__ __half g_eh[(size_t)BB * TT * TT];     // E = exp(scores) fp16
__device__ float  g_psum[(size_t)BB * 16 * TT];   // per-(batch,coltile) row partials
__device__ float  g_invsum[MTOT];                 // 1 / row sums of E
__device__ __half g_oh[(size_t)MTOT * NHC];

// ---------------------------------------------------------------------------
// PTX helpers (sm_80-era only — must be valid under compute_103 virtual arch)
// ---------------------------------------------------------------------------
__device__ __forceinline__ uint32_t smem_u32(const void* p) {
    uint32_t a;
    asm("{ .reg .u64 t; cvta.to.shared.u64 t, %1; cvt.u32.u64 %0, t; }"
        : "=r"(a) : "l"(p));
    return a;
}
__device__ __forceinline__ void cpa16(uint32_t dst, const void* src) {
    asm volatile("cp.async.cg.shared.global [%0], [%1], 16;\n" :: "r"(dst), "l"(src));
}
__device__ __forceinline__ void cpa_commit() {
    asm volatile("cp.async.commit_group;\n" ::: "memory");
}
template <int N>
__device__ __forceinline__ void cpa_wait() {
    asm volatile("cp.async.wait_group %0;\n" :: "n"(N) : "memory");
}
__device__ __forceinline__ void ldsm4(uint32_t* r, uint32_t addr) {
    asm volatile("ldmatrix.sync.aligned.m8n8.x4.shared.b16 {%0,%1,%2,%3}, [%4];"
                 : "=r"(r[0]), "=r"(r[1]), "=r"(r[2]), "=r"(r[3]) : "r"(addr));
}
// fp16 inputs, fp32 accumulate
__device__ __forceinline__ void mma16816(float* d, const uint32_t* a, const uint32_t* b) {
    asm volatile(
        "mma.sync.aligned.m16n8k16.row.col.f32.f16.f16.f32 "
        "{%0,%1,%2,%3}, {%4,%5,%6,%7}, {%8,%9}, {%0,%1,%2,%3};"
        : "+f"(d[0]), "+f"(d[1]), "+f"(d[2]), "+f"(d[3])
        : "r"(a[0]), "r"(a[1]), "r"(a[2]), "r"(a[3]), "r"(b[0]), "r"(b[1]));
}
__device__ __forceinline__ uint32_t swz(uint32_t off) {
    return off ^ ((off >> 3) & 0x70);
}

// ---------------------------------------------------------------------------
// PERSISTENT mma.sync NT GEMM (1-term fp16): C[M,N] = alpha*(A[M,K] @ B[N,K]^T)
// fp32 accumulate. Tile 128x128, 8 warps (4x2), warp tile 32x64, K chunks 64.
// Each CTA loops over tiles t = blockIdx.x + k*gridDim.x; the 3-slot cp.async
// ring runs CONTINUOUSLY across tile boundaries (loads for tile t+1 chunks 0-1
// are issued during tile t's last chunks), so the pipeline-fill bubble happens
// once per CTA, not once per tile.  ONE __syncthreads per chunk.
// Wait discipline: wait<1> steady-state; wait<0> only on the global last chunk.
// Tile decode: bx = t % TX, by = (t/TX) % TY, bz = t/(TX*TY).
// EXPOUT: epilogue writes exp(alpha*acc).  ROWSCALE: xRS[bz*TT+r].
// PSUM: scores-only — reduce per-row partial sums over this tile's 128 cols
// (shfl + smem) and write PS[(bz*TX+bx)*TT + row].
// __launch_bounds__(256, 2): 97 KB smem/CTA -> 2 CTAs/SM.
// ---------------------------------------------------------------------------
#define A_OFF 0
#define B_OFF 16384
#define STG   32768                   // 32 KB per stage
#define NSTAGE 3
#define SMEM_TOTAL (NSTAGE * STG + 1024)   // + 1 KB psum scratch

template <int OUTH, int EXPOUT, int ROWSCALE, int PSUM>
__global__ void __launch_bounds__(256, 2) gemm_mma(
    const __half* __restrict__ A, const __half* __restrict__ B,
    float* __restrict__ C, __half* __restrict__ Ch,
    const float* __restrict__ RS, float* __restrict__ PS,
    int K, int lda, int ldb, int ldc,
    long long sA, long long sB, long long sC, float alpha,
    int TX, int TY, int ntiles)
{
    extern __shared__ __align__(1024) char smem[];
    const uint32_t sbase = smem_u32(smem);
    const int tid = threadIdx.x;
    const int wid = tid >> 5, lane = tid & 31;
    const int G = gridDim.x;
    const long long ldab = (long long)lda * 2;
    const long long ldbb = (long long)ldb * 2;
    const int NC = K >> 6;

    // ---- load-side state (runs ahead of compute by 2 chunk-groups)
    int t_load = blockIdx.x, c_load = 0;
    const char *gAl, *gBl;
    {
        const int bx = t_load % TX;
        const int rr = t_load / TX;
        const int by = rr % TY;
        const long long bz = rr / TY;
        gAl = (const char*)(A + bz * sA + (long long)(by * 128) * lda);
        gBl = (const char*)(B + bz * sB + (long long)(bx * 128) * ldb);
    }
    uint32_t sb_l = sbase;

    auto issue_load = [&]() {
        if (t_load >= ntiles) return;
        const long long kb = (long long)c_load * 128;    // 64 fp16 = 128 B
#pragma unroll
        for (int i = 0; i < 4; i++) {
            const int id = tid + (i << 8);               // 0..1023
            const uint32_t r = id >> 3, cb = (id & 7) << 4;
            const uint32_t off = swz((r << 7) + cb);
            cpa16(sb_l + A_OFF + off, gAl + (long long)r * ldab + kb + cb);
            cpa16(sb_l + B_OFF + off, gBl + (long long)r * ldbb + kb + cb);
        }
        cpa_commit();
        sb_l += STG; if (sb_l == sbase + NSTAGE * STG) sb_l = sbase;
        if (++c_load == NC) {
            c_load = 0;
            t_load += G;
            if (t_load < ntiles) {
                const int bx = t_load % TX;
                const int rr = t_load / TX;
                const int by = rr % TY;
                const long long bz = rr / TY;
                gAl = (const char*)(A + bz * sA + (long long)(by * 128) * lda);
                gBl = (const char*)(B + bz * sB + (long long)(bx * 128) * ldb);
            }
        }
    };

    issue_load();
    issue_load();

    const int warp_m = wid & 3;       // 4 warps down M (32 rows each)
    const int warp_n = wid >> 2;      // 2 warps across N (64 cols each)
    const int lrow = lane & 15;
    const uint32_t klane = (lane >> 4) << 4;
    uint32_t sb_c = sbase;

    for (int t = blockIdx.x; t < ntiles; t += G) {
        const int bx = t % TX;
        const int rr = t / TX;
        const int by = rr % TY;
        const long long bz = rr / TY;
        const int row0 = by * 128, col0 = bx * 128;
        const bool last_tile = (t + G >= ntiles);

        float acc[2][8][4];
#pragma unroll
        for (int i = 0; i < 2; i++)
#pragma unroll
            for (int j = 0; j < 8; j++)
#pragma unroll
                for (int k = 0; k < 4; k++) acc[i][j][k] = 0.0f;

        for (int c = 0; c < NC; c++) {
            if (last_tile && c == NC - 1) cpa_wait<0>(); else cpa_wait<1>();
            __syncthreads();              // the ONLY barrier per chunk

            const uint32_t sb = sb_c;
#pragma unroll
            for (int ks = 0; ks < 4; ks++) {
                const uint32_t kbyte = (ks << 5) + klane;
                uint32_t ah[2][4];
#pragma unroll
                for (int mt = 0; mt < 2; mt++) {
                    const uint32_t off =
                        swz((uint32_t)((warp_m * 32 + mt * 16 + lrow) << 7) + kbyte);
                    ldsm4(ah[mt], sb + A_OFF + off);
                }
                uint32_t bh[4][4];
#pragma unroll
                for (int ng = 0; ng < 4; ng++) {
                    const uint32_t off =
                        swz((uint32_t)((warp_n * 64 + ng * 16 + lrow) << 7) + kbyte);
                    ldsm4(bh[ng], sb + B_OFF + off);
                }
#pragma unroll
                for (int mt = 0; mt < 2; mt++)
#pragma unroll
                    for (int nt = 0; nt < 8; nt++) {
                        const int ng = nt >> 1, j = nt & 1;
                        uint32_t B0[2] = { bh[ng][j], bh[ng][j + 2] };
                        mma16816(acc[mt][nt], ah[mt], B0);
                    }
            }

            issue_load();                 // ring continues across tile boundary
            sb_c += STG; if (sb_c == sbase + NSTAGE * STG) sb_c = sbase;
        }

        // ---- Epilogue: c-frag rows lane/4 (+8), cols 2*(lane%4)+1
        float rp[4];
        if (PSUM) { rp[0] = rp[1] = rp[2] = rp[3] = 0.0f; }
        const int rw = row0 + warp_m * 32 + (lane >> 2);
        const int cw = col0 + warp_n * 64 + (lane & 3) * 2;
#pragma unroll
        for (int mt = 0; mt < 2; mt++)
#pragma unroll
            for (int nt = 0; nt < 8; nt++) {
                const int cc = cw + nt * 8;
#pragma unroll
                for (int h = 0; h < 2; h++) {
                    const int r = rw + mt * 16 + h * 8;
                    float v0 = alpha * acc[mt][nt][h * 2 + 0];
                    float v1 = alpha * acc[mt][nt][h * 2 + 1];
                    if (EXPOUT) { v0 = __expf(v0); v1 = __expf(v1); }
                    if (ROWSCALE) { const float sc = RS[bz * TT + r]; v0 *= sc; v1 *= sc; }
                    if (PSUM) rp[mt * 2 + h] += v0 + v1;
                    const long long ci = bz * sC + (long long)r * ldc + cc;
                    if (OUTH) {
                        ushort2 H;
                        H.x = __half_as_ushort(__float2half(v0));
                        H.y = __half_as_ushort(__float2half(v1));
                        *(ushort2*)&Ch[ci] = H;
                    } else {
                        float2 o; o.x = v0; o.y = v1;
                        *(float2*)&C[ci] = o;
                    }
                }
            }

        if (PSUM) {
            // combine the 4 lanes (lane&3) covering the same row
#pragma unroll
            for (int i = 0; i < 4; i++) {
                rp[i] += __shfl_xor_sync(0xffffffffu, rp[i], 1);
                rp[i] += __shfl_xor_sync(0xffffffffu, rp[i], 2);
            }
            float* ps = (float*)(smem + NSTAGE * STG);   // [2][128]
            __syncthreads();                              // ps reuse across tiles
            if ((lane & 3) == 0) {
#pragma unroll
                for (int mt = 0; mt < 2; mt++)
#pragma unroll
                    for (int h = 0; h < 2; h++) {
                        const int lr = warp_m * 32 + mt * 16 + h * 8 + (lane >> 2);
                        ps[warp_n * 128 + lr] = rp[mt * 2 + h];
                    }
            }
            __syncthreads();
            if (tid < 128)
                PS[((long long)bz * TX + bx) * TT + row0 + tid] =
                    ps[tid] + ps[128 + tid];
        }
    }
}

// ---------------------------------------------------------------------------
// Fused fp32 -> fp16 convert of x + all weights in ONE launch.
// ---------------------------------------------------------------------------
__global__ void __launch_bounds__(256) split_all(
    const float* __restrict__ x,  const float* __restrict__ Wq,
    const float* __restrict__ Wk, const float* __restrict__ Wv,
    const float* __restrict__ Wo,
    __half* __restrict__ xh, __half* __restrict__ wqkh,
    __half* __restrict__ wvh, __half* __restrict__ woh)
{
    const int b = blockIdx.x;
    const int tid = threadIdx.x;
    const float4* in4;
    ushort4* h4;
    long long n4, i0, stride;
    if (b < 2048) {
        in4 = (const float4*)x;  h4 = (ushort4*)xh;
        n4 = (long long)MTOT * NXC / 4;  i0 = (long long)b * 256 + tid;  stride = 2048 * 256;
    } else {
        const int w = (b - 2048) >> 8;          // 0..3
        const int lb = (b - 2048) & 255;        // 0..255
        const float* W[4] = {Wq, Wk, Wv, Wo};
        __half* WH[4] = {wqkh, wqkh + (size_t)NHC * NXC, wvh, woh};
        in4 = (const float4*)W[w];  h4 = (ushort4*)WH[w];
        n4 = (long long)NHC * NXC / 4;  i0 = (long long)lb * 256 + tid;  stride = 256 * 256;
    }
    for (long long i = i0; i < n4; i += stride) {
        const float4 v = in4[i];
        ushort4 H;
        H.x = __half_as_ushort(__float2half(v.x));
        H.y = __half_as_ushort(__float2half(v.y));
        H.z = __half_as_ushort(__float2half(v.z));
        H.w = __half_as_ushort(__float2half(v.w));
        h4[i] = H;
    }
}

// ---------------------------------------------------------------------------
// Finalize: invsum[row] = 1 / sum over 16 col-tile partials.  1 MB read.
// ---------------------------------------------------------------------------
__global__ void __launch_bounds__(256) rowsum_final(
    const float* __restrict__ PS, float* __restrict__ invsum)
{
    const int row = blockIdx.x * 256 + threadIdx.x;   // 0..16383
    const int bz = row >> 11, r = row & 2047;
    float s = 0.0f;
#pragma unroll
    for (int i = 0; i < 16; i++)
        s += PS[((long long)bz * 16 + i) * TT + r];
    invsum[row] = 1.0f / s;
}

// ---------------------------------------------------------------------------
// Launch sequence (ncu captures launch #4 = SCORES):
//   1 split_all, 2 qk-proj, 3 v-proj, 4 SCORES(exp+psum), 5 rowsum_final,
//   6 pv (x invsum), 7 out
// ---------------------------------------------------------------------------
extern "C" void kernel_launch(void* const* d_in, const int* in_sizes, int n_in,
                              void* d_out, int out_size)
{
    (void)in_sizes; (void)n_in; (void)out_size;
    const float* x  = (const float*)d_in[0];
    const float* Wq = (const float*)d_in[1];
    const float* Wk = (const float*)d_in[2];
    const float* Wv = (const float*)d_in[3];
    const float* Wo = (const float*)d_in[4];
    float* out = (float*)d_out;

    __half *xh, *wqkh, *wvh, *woh, *qkh, *vth, *eh, *oh;
    float *psum, *invsum;
    cudaGetSymbolAddress((void**)&xh, g_xh);
    cudaGetSymbolAddress((void**)&wqkh, g_wqkh);
    cudaGetSymbolAddress((void**)&wvh, g_wvh);
    cudaGetSymbolAddress((void**)&woh, g_woh);
    cudaGetSymbolAddress((void**)&qkh, g_qkh);
    cudaGetSymbolAddress((void**)&vth, g_vth);
    cudaGetSymbolAddress((void**)&eh, g_eh);
    cudaGetSymbolAddress((void**)&oh, g_oh);
    cudaGetSymbolAddress((void**)&psum, g_psum);
    cudaGetSymbolAddress((void**)&invsum, g_invsum);

    int sms = 148;
    cudaDeviceGetAttribute(&sms, cudaDevAttrMultiProcessorCount, 0);
    const int GMAX = 2 * sms;

    cudaFuncSetAttribute(gemm_mma<1,0,0,0>, cudaFuncAttributeMaxDynamicSharedMemorySize, SMEM_TOTAL);
    cudaFuncSetAttribute(gemm_mma<1,1,0,1>, cudaFuncAttributeMaxDynamicSharedMemorySize, SMEM_TOTAL);
    cudaFuncSetAttribute(gemm_mma<1,0,1,0>, cudaFuncAttributeMaxDynamicSharedMemorySize, SMEM_TOTAL);
    cudaFuncSetAttribute(gemm_mma<0,0,0,0>, cudaFuncAttributeMaxDynamicSharedMemorySize, SMEM_TOTAL);

    const dim3 blk(256);

    // 1) fused converts
    split_all<<<3072, blk>>>(x, Wq, Wk, Wv, Wo, xh, wqkh, wvh, woh);

    // 2) merged qk = x @ [Wq;Wk]^T   [16384 x 2048]   TX=16, TY=128, 2048 tiles
    {
        const int tiles = 16 * 128;
        const int G = tiles < GMAX ? tiles : GMAX;
        gemm_mma<1,0,0,0><<<G, blk, SMEM_TOTAL>>>(xh, wqkh, nullptr, qkh, nullptr, nullptr,
                                                  NXC, NXC, NXC, 2 * NHC, 0, 0, 0, 1.0f,
                                                  16, 128, tiles);
    }

    // 3) vT = Wv @ x^T   [1024 x 16384]   TX=128, TY=8, 1024 tiles
    {
        const int tiles = 128 * 8;
        const int G = tiles < GMAX ? tiles : GMAX;
        gemm_mma<1,0,0,0><<<G, blk, SMEM_TOTAL>>>(wvh, xh, nullptr, vth, nullptr, nullptr,
                                                  NXC, NXC, NXC, MTOT, 0, 0, 0, 1.0f,
                                                  128, 8, tiles);
    }

    // 4) E_b = exp((q_b @ k_b^T)/sqrt(T)) + row partials   TX=16, TY=16, z=8
    {
        const int tiles = 16 * 16 * BB;
        const int G = tiles < GMAX ? tiles : GMAX;
        gemm_mma<1,1,0,1><<<G, blk, SMEM_TOTAL>>>(qkh, qkh + NHC, nullptr, eh, nullptr, psum,
                                                  NHC, 2 * NHC, 2 * NHC, TT,
                                                  (long long)TT * 2 * NHC,
                                                  (long long)TT * 2 * NHC,
                                                  (long long)TT * TT, 0.022097086912079608f,
                                                  16, 16, tiles);
    }

    // 5) invsum[row] = 1 / sum of 16 partials
    rowsum_final<<<MTOT / 256, blk>>>(psum, invsum);

    // 6) o_b = (E_b @ vT_b^T) * invsum   TX=8, TY=16, z=8
    {
        const int tiles = 8 * 16 * BB;
        const int G = tiles < GMAX ? tiles : GMAX;
        gemm_mma<1,0,1,0><<<G, blk, SMEM_TOTAL>>>(eh, vth, nullptr, oh, invsum, nullptr,
                                                  TT, TT, MTOT, NHC,
                                                  (long long)TT * TT, (long long)TT,
                                                  (long long)TT * NHC, 1.0f,
                                                  8, 16, tiles);
    }

    // 7) out = o @ Wo^T   [16384 x 1024], fp32 out   TX=8, TY=128
    {
        const int tiles = 8 * 128;
        const int G = tiles < GMAX ? tiles : GMAX;
        gemm_mma<0,0,0,0><<<G, blk, SMEM_TOTAL>>>(oh, woh, out, nullptr, nullptr, nullptr,
                                                  NHC, NHC, NHC, NHC, 0, 0, 0, 1.0f,
                                                  8, 128, tiles);
    }
}